// round 1
// baseline (speedup 1.0000x reference)
#include <cuda_runtime.h>
#include <math.h>

#define NB  16
#define NH  12
#define SEQ 1024
#define HD  64
#define ED  768

// Scratch (static device arrays — allocation-free per harness rules)
__device__ float g_q[(size_t)NB * NH * SEQ * HD];
__device__ float g_k[(size_t)NB * NH * SEQ * HD];
__device__ float g_v[(size_t)NB * NH * SEQ * HD];
__device__ float g_attn[(size_t)NB * SEQ * ED];

// ---------------------------------------------------------------------------
// 128x128x8 fp32 SGEMM, 256 threads, 8x8 micro-tile per thread.
// QKV variant: C = x @ w_qkv + b_qkv, scattered into g_q/g_k/g_v [B,H,N,D].
// ---------------------------------------------------------------------------
__global__ __launch_bounds__(256) void qkv_gemm_kernel(
    const float* __restrict__ A,      // x  [16384, 768]
    const float* __restrict__ B,      // w_qkv [768, 2304]
    const float* __restrict__ bias)   // b_qkv [2304]
{
    const int K = ED, Nn = 3 * ED;
    __shared__ float As[8][132];
    __shared__ float Bs[8][128];

    const int tid = threadIdx.x;
    const int tx = tid & 15, ty = tid >> 4;
    const int m0 = blockIdx.y * 128, n0 = blockIdx.x * 128;

    float acc[8][8];
#pragma unroll
    for (int i = 0; i < 8; i++)
#pragma unroll
        for (int j = 0; j < 8; j++) acc[i][j] = 0.0f;

    const int arow = tid >> 1;          // 0..127
    const int akp  = (tid & 1) * 4;     // 0 or 4
    const int brow = tid >> 5;          // 0..7
    const int bcol = (tid & 31) * 4;    // 0..124

    for (int k0 = 0; k0 < K; k0 += 8) {
        float4 a = *(const float4*)&A[(size_t)(m0 + arow) * K + k0 + akp];
        As[akp + 0][arow] = a.x;
        As[akp + 1][arow] = a.y;
        As[akp + 2][arow] = a.z;
        As[akp + 3][arow] = a.w;
        *(float4*)&Bs[brow][bcol] =
            *(const float4*)&B[(size_t)(k0 + brow) * Nn + n0 + bcol];
        __syncthreads();
#pragma unroll
        for (int kk = 0; kk < 8; kk++) {
            float af[8], bf[8];
            *(float4*)&af[0] = *(float4*)&As[kk][ty * 4];
            *(float4*)&af[4] = *(float4*)&As[kk][ty * 4 + 64];
            *(float4*)&bf[0] = *(float4*)&Bs[kk][tx * 4];
            *(float4*)&bf[4] = *(float4*)&Bs[kk][tx * 4 + 64];
#pragma unroll
            for (int i = 0; i < 8; i++)
#pragma unroll
                for (int j = 0; j < 8; j++)
                    acc[i][j] += af[i] * bf[j];
        }
        __syncthreads();
    }

    // Epilogue: bias + scatter to q/k/v in [B,H,N,D]
#pragma unroll
    for (int i = 0; i < 8; i++) {
        int row = m0 + ty * 4 + (i & 3) + (i >> 2) * 64;
        int b = row >> 10, nn = row & 1023;
#pragma unroll
        for (int j = 0; j < 8; j++) {
            int n = n0 + tx * 4 + (j & 3) + (j >> 2) * 64;
            float v = acc[i][j] + bias[n];
            int which = n / ED;
            int e = n - which * ED;
            int h = e >> 6, d = e & 63;
            float* dst = (which == 0) ? g_q : ((which == 1) ? g_k : g_v);
            dst[((((size_t)b * NH + h) * SEQ + nn) << 6) + d] = v;
        }
    }
}

// ---------------------------------------------------------------------------
// Projection SGEMM: out = g_attn @ w_proj + b_proj
// ---------------------------------------------------------------------------
__global__ __launch_bounds__(256) void proj_gemm_kernel(
    const float* __restrict__ B,      // w_proj [768, 768]
    const float* __restrict__ bias,   // b_proj [768]
    float* __restrict__ out)          // [16384, 768]
{
    const int K = ED, Nn = ED;
    const float* A = g_attn;
    __shared__ float As[8][132];
    __shared__ float Bs[8][128];

    const int tid = threadIdx.x;
    const int tx = tid & 15, ty = tid >> 4;
    const int m0 = blockIdx.y * 128, n0 = blockIdx.x * 128;

    float acc[8][8];
#pragma unroll
    for (int i = 0; i < 8; i++)
#pragma unroll
        for (int j = 0; j < 8; j++) acc[i][j] = 0.0f;

    const int arow = tid >> 1;
    const int akp  = (tid & 1) * 4;
    const int brow = tid >> 5;
    const int bcol = (tid & 31) * 4;

    for (int k0 = 0; k0 < K; k0 += 8) {
        float4 a = *(const float4*)&A[(size_t)(m0 + arow) * K + k0 + akp];
        As[akp + 0][arow] = a.x;
        As[akp + 1][arow] = a.y;
        As[akp + 2][arow] = a.z;
        As[akp + 3][arow] = a.w;
        *(float4*)&Bs[brow][bcol] =
            *(const float4*)&B[(size_t)(k0 + brow) * Nn + n0 + bcol];
        __syncthreads();
#pragma unroll
        for (int kk = 0; kk < 8; kk++) {
            float af[8], bf[8];
            *(float4*)&af[0] = *(float4*)&As[kk][ty * 4];
            *(float4*)&af[4] = *(float4*)&As[kk][ty * 4 + 64];
            *(float4*)&bf[0] = *(float4*)&Bs[kk][tx * 4];
            *(float4*)&bf[4] = *(float4*)&Bs[kk][tx * 4 + 64];
#pragma unroll
            for (int i = 0; i < 8; i++)
#pragma unroll
                for (int j = 0; j < 8; j++)
                    acc[i][j] += af[i] * bf[j];
        }
        __syncthreads();
    }

#pragma unroll
    for (int i = 0; i < 8; i++) {
        int row = m0 + ty * 4 + (i & 3) + (i >> 2) * 64;
#pragma unroll
        for (int j = 0; j < 8; j++) {
            int n = n0 + tx * 4 + (j & 3) + (j >> 2) * 64;
            out[(size_t)row * Nn + n] = acc[i][j] + bias[n];
        }
    }
}

// ---------------------------------------------------------------------------
// Flash-attention kernel: one block per (b, h, 64-row Q tile).
// 256 threads: thread (ty,tx) owns S rows ty*4..+3 x cols tx*4..+3,
// and O rows ty*4..+3 x dims tx*4..+3.
// ---------------------------------------------------------------------------
#define ATTN_STRIDE 68
#define ATTN_SMEM_FLOATS (4 * 64 * ATTN_STRIDE)

__global__ __launch_bounds__(256) void attn_kernel()
{
    extern __shared__ float smem[];
    float* Qs = smem;                               // [64][68]
    float* Ks = smem + 64 * ATTN_STRIDE;            // [64][68]
    float* Vs = smem + 2 * 64 * ATTN_STRIDE;        // [64][68]
    float* Ps = smem + 3 * 64 * ATTN_STRIDE;        // [64][68]

    const int tid = threadIdx.x;
    const int tx = tid & 15, ty = tid >> 4;
    const int n0 = blockIdx.x * 64;
    const int bh = blockIdx.z * NH + blockIdx.y;

    const float* Q = g_q + (size_t)bh * SEQ * HD;
    const float* Kg = g_k + (size_t)bh * SEQ * HD;
    const float* Vg = g_v + (size_t)bh * SEQ * HD;

    // Load Q tile: coalesced, 4 float4 per thread
#pragma unroll
    for (int l = 0; l < 4; l++) {
        int idx = tid + 256 * l;      // 0..1023
        int r = idx >> 4;             // 0..63
        int c = (idx & 15) * 4;       // 0..60
        *(float4*)&Qs[r * ATTN_STRIDE + c] =
            *(const float4*)&Q[(size_t)(n0 + r) * HD + c];
    }

    float m[4], lsum[4];
    float O[4][4];
#pragma unroll
    for (int i = 0; i < 4; i++) {
        m[i] = -1e30f;
        lsum[i] = 0.0f;
#pragma unroll
        for (int c = 0; c < 4; c++) O[i][c] = 0.0f;
    }

    const float scale = 0.125f; // 1/sqrt(64)

    for (int j0 = 0; j0 < SEQ; j0 += 64) {
        __syncthreads();  // protect Ks/Vs/Ps from previous iteration's readers
#pragma unroll
        for (int l = 0; l < 4; l++) {
            int idx = tid + 256 * l;
            int r = idx >> 4;
            int c = (idx & 15) * 4;
            *(float4*)&Ks[r * ATTN_STRIDE + c] =
                *(const float4*)&Kg[(size_t)(j0 + r) * HD + c];
            *(float4*)&Vs[r * ATTN_STRIDE + c] =
                *(const float4*)&Vg[(size_t)(j0 + r) * HD + c];
        }
        __syncthreads();

        // S = Q K^T (4x4 per thread)
        float s[4][4];
#pragma unroll
        for (int i = 0; i < 4; i++)
#pragma unroll
            for (int j = 0; j < 4; j++) s[i][j] = 0.0f;

#pragma unroll
        for (int d = 0; d < HD; d += 4) {
            float4 q[4], k[4];
#pragma unroll
            for (int i = 0; i < 4; i++)
                q[i] = *(float4*)&Qs[(ty * 4 + i) * ATTN_STRIDE + d];
#pragma unroll
            for (int j = 0; j < 4; j++)
                k[j] = *(float4*)&Ks[(tx * 4 + j) * ATTN_STRIDE + d];
#pragma unroll
            for (int i = 0; i < 4; i++)
#pragma unroll
                for (int j = 0; j < 4; j++)
                    s[i][j] += q[i].x * k[j].x + q[i].y * k[j].y +
                               q[i].z * k[j].z + q[i].w * k[j].w;
        }

        // Online softmax per row (reduce across 16 tx lanes within warp)
#pragma unroll
        for (int i = 0; i < 4; i++) {
            float mx = s[i][0];
#pragma unroll
            for (int j = 1; j < 4; j++) mx = fmaxf(mx, s[i][j]);
            mx *= scale;
#pragma unroll
            for (int msk = 8; msk >= 1; msk >>= 1)
                mx = fmaxf(mx, __shfl_xor_sync(0xffffffffu, mx, msk));

            float mnew = fmaxf(m[i], mx);
            float corr = __expf(m[i] - mnew);
            m[i] = mnew;

            float rs = 0.0f;
#pragma unroll
            for (int j = 0; j < 4; j++) {
                float p = __expf(s[i][j] * scale - mnew);
                s[i][j] = p;
                rs += p;
            }
#pragma unroll
            for (int msk = 8; msk >= 1; msk >>= 1)
                rs += __shfl_xor_sync(0xffffffffu, rs, msk);

            lsum[i] = lsum[i] * corr + rs;
#pragma unroll
            for (int c = 0; c < 4; c++) O[i][c] *= corr;

            *(float4*)&Ps[(ty * 4 + i) * ATTN_STRIDE + tx * 4] =
                make_float4(s[i][0], s[i][1], s[i][2], s[i][3]);
        }
        __syncthreads();

        // O += P @ V (4x4 per thread)
#pragma unroll
        for (int j = 0; j < 64; j += 4) {
            float4 p[4], v[4];
#pragma unroll
            for (int i = 0; i < 4; i++)
                p[i] = *(float4*)&Ps[(ty * 4 + i) * ATTN_STRIDE + j];
#pragma unroll
            for (int jj = 0; jj < 4; jj++)
                v[jj] = *(float4*)&Vs[(j + jj) * ATTN_STRIDE + tx * 4];
#pragma unroll
            for (int i = 0; i < 4; i++) {
                O[i][0] += p[i].x * v[0].x + p[i].y * v[1].x +
                           p[i].z * v[2].x + p[i].w * v[3].x;
                O[i][1] += p[i].x * v[0].y + p[i].y * v[1].y +
                           p[i].z * v[2].y + p[i].w * v[3].y;
                O[i][2] += p[i].x * v[0].z + p[i].y * v[1].z +
                           p[i].z * v[2].z + p[i].w * v[3].z;
                O[i][3] += p[i].x * v[0].w + p[i].y * v[1].w +
                           p[i].z * v[2].w + p[i].w * v[3].w;
            }
        }
    }

    // Normalize and write to g_attn [B, N, H*D]
#pragma unroll
    for (int i = 0; i < 4; i++) {
        float inv = 1.0f / lsum[i];
        int row = n0 + ty * 4 + i;
        float4 o = make_float4(O[i][0] * inv, O[i][1] * inv,
                               O[i][2] * inv, O[i][3] * inv);
        *(float4*)&g_attn[((size_t)blockIdx.z * SEQ + row) * ED +
                          blockIdx.y * HD + tx * 4] = o;
    }
}

// ---------------------------------------------------------------------------
extern "C" void kernel_launch(void* const* d_in, const int* in_sizes, int n_in,
                              void* d_out, int out_size)
{
    const float* x      = (const float*)d_in[0];
    const float* w_qkv  = (const float*)d_in[1];
    const float* b_qkv  = (const float*)d_in[2];
    const float* w_proj = (const float*)d_in[3];
    const float* b_proj = (const float*)d_in[4];
    float* out = (float*)d_out;

    // 1) QKV GEMM + bias + scatter
    dim3 g1((3 * ED) / 128, (NB * SEQ) / 128);   // (18, 128)
    qkv_gemm_kernel<<<g1, 256>>>(x, w_qkv, b_qkv);

    // 2) Attention
    size_t smem = ATTN_SMEM_FLOATS * sizeof(float);  // 69632 B
    cudaFuncSetAttribute(attn_kernel,
                         cudaFuncAttributeMaxDynamicSharedMemorySize,
                         (int)smem);
    attn_kernel<<<dim3(SEQ / 64, NH, NB), 256, smem>>>();

    // 3) Output projection
    dim3 g3(ED / 128, (NB * SEQ) / 128);         // (6, 128)
    proj_gemm_kernel<<<g3, 256>>>(w_proj, b_proj, out);
}

// round 2
// speedup vs baseline: 3.7162x; 3.7162x over previous
#include <cuda_runtime.h>
#include <math.h>
#include <stdint.h>

#define NB  16
#define NH  12
#define SEQ 1024
#define HD  64
#define ED  768

// Scratch (static device arrays — allocation-free per harness rules)
__device__ float g_q[(size_t)NB * NH * SEQ * HD];
__device__ float g_k[(size_t)NB * NH * SEQ * HD];
__device__ float g_v[(size_t)NB * NH * SEQ * HD];
__device__ float g_attn[(size_t)NB * SEQ * ED];

// ---------------------------------------------------------------------------
// helpers
// ---------------------------------------------------------------------------
__device__ __forceinline__ uint32_t f2tf(float f) {
    uint32_t u;
    asm("cvt.rna.tf32.f32 %0, %1;" : "=r"(u) : "f"(f));
    return u;
}

__device__ __forceinline__ void mma_tf32(float* c, const uint32_t* a,
                                         const uint32_t* b) {
    asm volatile(
        "mma.sync.aligned.m16n8k8.row.col.f32.tf32.tf32.f32 "
        "{%0,%1,%2,%3}, {%4,%5,%6,%7}, {%8,%9}, {%0,%1,%2,%3};\n"
        : "+f"(c[0]), "+f"(c[1]), "+f"(c[2]), "+f"(c[3])
        : "r"(a[0]), "r"(a[1]), "r"(a[2]), "r"(a[3]), "r"(b[0]), "r"(b[1]));
}

// ---------------------------------------------------------------------------
// TF32 tensor-core GEMM, 128x128 tile, Ktile=32, 8 warps each 64x32.
// ---------------------------------------------------------------------------
#define AS_STRIDE 36
#define BS_STRIDE 136

// QKV variant: C = x @ w_qkv + b_qkv, scattered into g_q/g_k/g_v [B,H,N,D]
__global__ __launch_bounds__(256) void qkv_gemm_kernel(
    const float* __restrict__ A,      // x  [16384, 768]
    const float* __restrict__ B,      // w_qkv [768, 2304]
    const float* __restrict__ bias)   // b_qkv [2304]
{
    const int K = ED, Nn = 3 * ED;
    __shared__ uint32_t As[128][AS_STRIDE];
    __shared__ uint32_t Bs[32][BS_STRIDE];

    const int tid = threadIdx.x;
    const int lane = tid & 31, wid = tid >> 5;
    const int wm = wid >> 2, wn = wid & 3;       // warp tile: 64x32
    const int q = lane >> 2, t = lane & 3;
    const int m0 = blockIdx.y * 128, n0 = blockIdx.x * 128;

    float acc[4][4][4];
#pragma unroll
    for (int i = 0; i < 4; i++)
#pragma unroll
        for (int j = 0; j < 4; j++)
#pragma unroll
            for (int r = 0; r < 4; r++) acc[i][j][r] = 0.0f;

    for (int k0 = 0; k0 < K; k0 += 32) {
#pragma unroll
        for (int l = 0; l < 4; l++) {
            int lin = tid + 256 * l;             // 0..1023
            int r = lin >> 3, c = (lin & 7) * 4;
            float4 v = *(const float4*)&A[(size_t)(m0 + r) * K + k0 + c];
            As[r][c + 0] = f2tf(v.x);
            As[r][c + 1] = f2tf(v.y);
            As[r][c + 2] = f2tf(v.z);
            As[r][c + 3] = f2tf(v.w);
        }
#pragma unroll
        for (int l = 0; l < 4; l++) {
            int lin = tid + 256 * l;
            int kr = lin >> 5, c = (lin & 31) * 4;
            float4 v = *(const float4*)&B[(size_t)(k0 + kr) * Nn + n0 + c];
            Bs[kr][c + 0] = f2tf(v.x);
            Bs[kr][c + 1] = f2tf(v.y);
            Bs[kr][c + 2] = f2tf(v.z);
            Bs[kr][c + 3] = f2tf(v.w);
        }
        __syncthreads();

#pragma unroll
        for (int ks = 0; ks < 4; ks++) {
            int kk = ks * 8;
            uint32_t af[4][4];
#pragma unroll
            for (int mt = 0; mt < 4; mt++) {
                int rb = wm * 64 + mt * 16 + q;
                af[mt][0] = As[rb][kk + t];
                af[mt][1] = As[rb + 8][kk + t];
                af[mt][2] = As[rb][kk + 4 + t];
                af[mt][3] = As[rb + 8][kk + 4 + t];
            }
            uint32_t bf[4][2];
#pragma unroll
            for (int nt = 0; nt < 4; nt++) {
                int cb = wn * 32 + nt * 8 + q;
                bf[nt][0] = Bs[kk + t][cb];
                bf[nt][1] = Bs[kk + 4 + t][cb];
            }
#pragma unroll
            for (int mt = 0; mt < 4; mt++)
#pragma unroll
                for (int nt = 0; nt < 4; nt++)
                    mma_tf32(acc[mt][nt], af[mt], bf[nt]);
        }
        __syncthreads();
    }

    // Epilogue: bias + scatter to q/k/v in [B,H,N,D]
#pragma unroll
    for (int mt = 0; mt < 4; mt++) {
#pragma unroll
        for (int half = 0; half < 2; half++) {
            int row = m0 + wm * 64 + mt * 16 + q + half * 8;
            int b = row >> 10, nn = row & 1023;
#pragma unroll
            for (int nt = 0; nt < 4; nt++) {
                int n = n0 + wn * 32 + nt * 8 + 2 * t;
                float c0 = acc[mt][nt][half * 2 + 0] + bias[n];
                float c1 = acc[mt][nt][half * 2 + 1] + bias[n + 1];
                int which = n / ED;
                int e = n - which * ED;
                int h = e >> 6, d = e & 63;
                float* dst = (which == 0) ? g_q : ((which == 1) ? g_k : g_v);
                *(float2*)&dst[((((size_t)b * NH + h) * SEQ + nn) << 6) + d] =
                    make_float2(c0, c1);
            }
        }
    }
}

// Projection: out = g_attn @ w_proj + b_proj
__global__ __launch_bounds__(256) void proj_gemm_kernel(
    const float* __restrict__ B,      // w_proj [768, 768]
    const float* __restrict__ bias,   // b_proj [768]
    float* __restrict__ out)          // [16384, 768]
{
    const int K = ED, Nn = ED;
    const float* A = g_attn;
    __shared__ uint32_t As[128][AS_STRIDE];
    __shared__ uint32_t Bs[32][BS_STRIDE];

    const int tid = threadIdx.x;
    const int lane = tid & 31, wid = tid >> 5;
    const int wm = wid >> 2, wn = wid & 3;
    const int q = lane >> 2, t = lane & 3;
    const int m0 = blockIdx.y * 128, n0 = blockIdx.x * 128;

    float acc[4][4][4];
#pragma unroll
    for (int i = 0; i < 4; i++)
#pragma unroll
        for (int j = 0; j < 4; j++)
#pragma unroll
            for (int r = 0; r < 4; r++) acc[i][j][r] = 0.0f;

    for (int k0 = 0; k0 < K; k0 += 32) {
#pragma unroll
        for (int l = 0; l < 4; l++) {
            int lin = tid + 256 * l;
            int r = lin >> 3, c = (lin & 7) * 4;
            float4 v = *(const float4*)&A[(size_t)(m0 + r) * K + k0 + c];
            As[r][c + 0] = f2tf(v.x);
            As[r][c + 1] = f2tf(v.y);
            As[r][c + 2] = f2tf(v.z);
            As[r][c + 3] = f2tf(v.w);
        }
#pragma unroll
        for (int l = 0; l < 4; l++) {
            int lin = tid + 256 * l;
            int kr = lin >> 5, c = (lin & 31) * 4;
            float4 v = *(const float4*)&B[(size_t)(k0 + kr) * Nn + n0 + c];
            Bs[kr][c + 0] = f2tf(v.x);
            Bs[kr][c + 1] = f2tf(v.y);
            Bs[kr][c + 2] = f2tf(v.z);
            Bs[kr][c + 3] = f2tf(v.w);
        }
        __syncthreads();

#pragma unroll
        for (int ks = 0; ks < 4; ks++) {
            int kk = ks * 8;
            uint32_t af[4][4];
#pragma unroll
            for (int mt = 0; mt < 4; mt++) {
                int rb = wm * 64 + mt * 16 + q;
                af[mt][0] = As[rb][kk + t];
                af[mt][1] = As[rb + 8][kk + t];
                af[mt][2] = As[rb][kk + 4 + t];
                af[mt][3] = As[rb + 8][kk + 4 + t];
            }
            uint32_t bf[4][2];
#pragma unroll
            for (int nt = 0; nt < 4; nt++) {
                int cb = wn * 32 + nt * 8 + q;
                bf[nt][0] = Bs[kk + t][cb];
                bf[nt][1] = Bs[kk + 4 + t][cb];
            }
#pragma unroll
            for (int mt = 0; mt < 4; mt++)
#pragma unroll
                for (int nt = 0; nt < 4; nt++)
                    mma_tf32(acc[mt][nt], af[mt], bf[nt]);
        }
        __syncthreads();
    }

#pragma unroll
    for (int mt = 0; mt < 4; mt++) {
#pragma unroll
        for (int half = 0; half < 2; half++) {
            int row = m0 + wm * 64 + mt * 16 + q + half * 8;
#pragma unroll
            for (int nt = 0; nt < 4; nt++) {
                int n = n0 + wn * 32 + nt * 8 + 2 * t;
                float c0 = acc[mt][nt][half * 2 + 0] + bias[n];
                float c1 = acc[mt][nt][half * 2 + 1] + bias[n + 1];
                *(float2*)&out[(size_t)row * Nn + n] = make_float2(c0, c1);
            }
        }
    }
}

// ---------------------------------------------------------------------------
// Flash attention with TF32 mma. Block = 128 Q rows x (b,h). 8 warps,
// warp w owns rows [w*16, w*16+16). KV tiles of 64.
// ---------------------------------------------------------------------------
#define QS_STR 68
#define KS_STR 68
#define VS_STR 72
#define PS_STR 68
// u32 words: Qs 128*68, Ks 64*68, Vs 64*72, Ps 128*68
#define SM_QS 0
#define SM_KS (128 * QS_STR)
#define SM_VS (SM_KS + 64 * KS_STR)
#define SM_PS (SM_VS + 64 * VS_STR)
#define ATTN_SMEM_WORDS (SM_PS + 128 * PS_STR)

__global__ __launch_bounds__(256, 2) void attn_kernel()
{
    extern __shared__ uint32_t sm[];
    uint32_t* Qs = sm + SM_QS;
    uint32_t* Ks = sm + SM_KS;
    uint32_t* Vs = sm + SM_VS;
    uint32_t* Ps = sm + SM_PS;

    const int tid = threadIdx.x;
    const int lane = tid & 31, w = tid >> 5;
    const int q = lane >> 2, t = lane & 3;
    const int n0 = blockIdx.x * 128;
    const int bh = blockIdx.z * NH + blockIdx.y;
    const int mb = w * 16;

    const float* Q = g_q + (size_t)bh * SEQ * HD;
    const float* Kg = g_k + (size_t)bh * SEQ * HD;
    const float* Vg = g_v + (size_t)bh * SEQ * HD;

    // Load Q tile (128x64), convert to tf32
#pragma unroll
    for (int l = 0; l < 8; l++) {
        int lin = tid + 256 * l;          // 0..2047
        int r = lin >> 4, c = (lin & 15) * 4;
        float4 v = *(const float4*)&Q[(size_t)(n0 + r) * HD + c];
        Qs[r * QS_STR + c + 0] = f2tf(v.x);
        Qs[r * QS_STR + c + 1] = f2tf(v.y);
        Qs[r * QS_STR + c + 2] = f2tf(v.z);
        Qs[r * QS_STR + c + 3] = f2tf(v.w);
    }

    float oacc[8][4];
#pragma unroll
    for (int nt = 0; nt < 8; nt++)
#pragma unroll
        for (int r = 0; r < 4; r++) oacc[nt][r] = 0.0f;
    float m0_ = -1e30f, m1_ = -1e30f, l0_ = 0.0f, l1_ = 0.0f;

    const float sc = 0.125f * 1.4426950408889634f;  // scale * log2(e)

    for (int j0 = 0; j0 < SEQ; j0 += 64) {
        __syncthreads();   // protect Ks/Vs from previous iteration readers
#pragma unroll
        for (int l = 0; l < 4; l++) {
            int lin = tid + 256 * l;
            int r = lin >> 4, c = (lin & 15) * 4;
            float4 kv = *(const float4*)&Kg[(size_t)(j0 + r) * HD + c];
            Ks[r * KS_STR + c + 0] = f2tf(kv.x);
            Ks[r * KS_STR + c + 1] = f2tf(kv.y);
            Ks[r * KS_STR + c + 2] = f2tf(kv.z);
            Ks[r * KS_STR + c + 3] = f2tf(kv.w);
            float4 vv = *(const float4*)&Vg[(size_t)(j0 + r) * HD + c];
            Vs[r * VS_STR + c + 0] = f2tf(vv.x);
            Vs[r * VS_STR + c + 1] = f2tf(vv.y);
            Vs[r * VS_STR + c + 2] = f2tf(vv.z);
            Vs[r * VS_STR + c + 3] = f2tf(vv.w);
        }
        __syncthreads();

        // S = Q K^T   (warp: 16 rows x 64 cols)
        float sacc[8][4];
#pragma unroll
        for (int nt = 0; nt < 8; nt++)
#pragma unroll
            for (int r = 0; r < 4; r++) sacc[nt][r] = 0.0f;

#pragma unroll
        for (int ks = 0; ks < 8; ks++) {
            int kk = ks * 8;
            uint32_t a[4];
            int ar = mb + q;
            a[0] = Qs[ar * QS_STR + kk + t];
            a[1] = Qs[(ar + 8) * QS_STR + kk + t];
            a[2] = Qs[ar * QS_STR + kk + 4 + t];
            a[3] = Qs[(ar + 8) * QS_STR + kk + 4 + t];
#pragma unroll
            for (int nt = 0; nt < 8; nt++) {
                int nb = nt * 8 + q;
                uint32_t b[2];
                b[0] = Ks[nb * KS_STR + kk + t];
                b[1] = Ks[nb * KS_STR + kk + 4 + t];
                mma_tf32(sacc[nt], a, b);
            }
        }

        // scale into log2 domain
#pragma unroll
        for (int nt = 0; nt < 8; nt++)
#pragma unroll
            for (int r = 0; r < 4; r++) sacc[nt][r] *= sc;

        // online softmax: row0 = mb+q (c0,c1), row1 = mb+8+q (c2,c3)
        float mx0 = -1e30f, mx1 = -1e30f;
#pragma unroll
        for (int nt = 0; nt < 8; nt++) {
            mx0 = fmaxf(mx0, fmaxf(sacc[nt][0], sacc[nt][1]));
            mx1 = fmaxf(mx1, fmaxf(sacc[nt][2], sacc[nt][3]));
        }
#pragma unroll
        for (int off = 1; off <= 2; off <<= 1) {
            mx0 = fmaxf(mx0, __shfl_xor_sync(0xffffffffu, mx0, off));
            mx1 = fmaxf(mx1, __shfl_xor_sync(0xffffffffu, mx1, off));
        }
        float mn0 = fmaxf(m0_, mx0), mn1 = fmaxf(m1_, mx1);
        float corr0 = exp2f(m0_ - mn0), corr1 = exp2f(m1_ - mn1);
        m0_ = mn0; m1_ = mn1;

        float rs0 = 0.0f, rs1 = 0.0f;
#pragma unroll
        for (int nt = 0; nt < 8; nt++) {
            float p0 = exp2f(sacc[nt][0] - mn0);
            float p1 = exp2f(sacc[nt][1] - mn0);
            float p2 = exp2f(sacc[nt][2] - mn1);
            float p3 = exp2f(sacc[nt][3] - mn1);
            rs0 += p0 + p1;
            rs1 += p2 + p3;
            // store P (tf32) — warp-private rows
            uint2 lo = make_uint2(f2tf(p0), f2tf(p1));
            uint2 hi = make_uint2(f2tf(p2), f2tf(p3));
            *(uint2*)&Ps[(mb + q) * PS_STR + nt * 8 + 2 * t] = lo;
            *(uint2*)&Ps[(mb + 8 + q) * PS_STR + nt * 8 + 2 * t] = hi;
        }
#pragma unroll
        for (int off = 1; off <= 2; off <<= 1) {
            rs0 += __shfl_xor_sync(0xffffffffu, rs0, off);
            rs1 += __shfl_xor_sync(0xffffffffu, rs1, off);
        }
        l0_ = l0_ * corr0 + rs0;
        l1_ = l1_ * corr1 + rs1;
#pragma unroll
        for (int nt = 0; nt < 8; nt++) {
            oacc[nt][0] *= corr0;
            oacc[nt][1] *= corr0;
            oacc[nt][2] *= corr1;
            oacc[nt][3] *= corr1;
        }
        __syncwarp();

        // O += P @ V
#pragma unroll
        for (int ks = 0; ks < 8; ks++) {
            int kk = ks * 8;
            uint32_t a[4];
            int ar = mb + q;
            a[0] = Ps[ar * PS_STR + kk + t];
            a[1] = Ps[(ar + 8) * PS_STR + kk + t];
            a[2] = Ps[ar * PS_STR + kk + 4 + t];
            a[3] = Ps[(ar + 8) * PS_STR + kk + 4 + t];
#pragma unroll
            for (int nt = 0; nt < 8; nt++) {
                int nb = nt * 8 + q;
                uint32_t b[2];
                b[0] = Vs[(kk + t) * VS_STR + nb];
                b[1] = Vs[(kk + 4 + t) * VS_STR + nb];
                mma_tf32(oacc[nt], a, b);
            }
        }
    }

    // Normalize + write to g_attn [B, N, H*D]
    float inv0 = 1.0f / l0_, inv1 = 1.0f / l1_;
    int row0 = n0 + mb + q, row1 = row0 + 8;
    size_t base0 = ((size_t)blockIdx.z * SEQ + row0) * ED + blockIdx.y * HD;
    size_t base1 = ((size_t)blockIdx.z * SEQ + row1) * ED + blockIdx.y * HD;
#pragma unroll
    for (int nt = 0; nt < 8; nt++) {
        int col = nt * 8 + 2 * t;
        *(float2*)&g_attn[base0 + col] =
            make_float2(oacc[nt][0] * inv0, oacc[nt][1] * inv0);
        *(float2*)&g_attn[base1 + col] =
            make_float2(oacc[nt][2] * inv1, oacc[nt][3] * inv1);
    }
}

// ---------------------------------------------------------------------------
extern "C" void kernel_launch(void* const* d_in, const int* in_sizes, int n_in,
                              void* d_out, int out_size)
{
    const float* x      = (const float*)d_in[0];
    const float* w_qkv  = (const float*)d_in[1];
    const float* b_qkv  = (const float*)d_in[2];
    const float* w_proj = (const float*)d_in[3];
    const float* b_proj = (const float*)d_in[4];
    float* out = (float*)d_out;

    // 1) QKV GEMM + bias + scatter
    dim3 g1((3 * ED) / 128, (NB * SEQ) / 128);   // (18, 128)
    qkv_gemm_kernel<<<g1, 256>>>(x, w_qkv, b_qkv);

    // 2) Attention
    size_t smem = (size_t)ATTN_SMEM_WORDS * 4;   // ~105 KB
    cudaFuncSetAttribute(attn_kernel,
                         cudaFuncAttributeMaxDynamicSharedMemorySize,
                         (int)smem);
    attn_kernel<<<dim3(SEQ / 128, NH, NB), 256, smem>>>();

    // 3) Output projection
    dim3 g3(ED / 128, (NB * SEQ) / 128);         // (6, 128)
    proj_gemm_kernel<<<g3, 256>>>(w_proj, b_proj, out);
}

// round 5
// speedup vs baseline: 4.0681x; 1.0947x over previous
#include <cuda_runtime.h>
#include <math.h>
#include <stdint.h>

#define NB  16
#define NH  12
#define SEQ 1024
#define HD  64
#define ED  768

__device__ float g_q[(size_t)NB * NH * SEQ * HD];
__device__ float g_k[(size_t)NB * NH * SEQ * HD];
__device__ float g_v[(size_t)NB * NH * SEQ * HD];
__device__ float g_attn[(size_t)NB * SEQ * ED];

__device__ __forceinline__ uint32_t f2tf(float f) {
    uint32_t u;
    asm("cvt.rna.tf32.f32 %0, %1;" : "=r"(u) : "f"(f));
    return u;
}

__device__ __forceinline__ void mma_tf32(float* c, uint32_t a0, uint32_t a1,
                                         uint32_t a2, uint32_t a3,
                                         uint32_t b0, uint32_t b1) {
    asm volatile(
        "mma.sync.aligned.m16n8k8.row.col.f32.tf32.tf32.f32 "
        "{%0,%1,%2,%3}, {%4,%5,%6,%7}, {%8,%9}, {%0,%1,%2,%3};\n"
        : "+f"(c[0]), "+f"(c[1]), "+f"(c[2]), "+f"(c[3])
        : "r"(a0), "r"(a1), "r"(a2), "r"(a3), "r"(b0), "r"(b1));
}

// ldmatrix.x4 on row-major fp32 smem: each 8x8-b16 tile == 8 rows x 4 tf32.
// reg j of lane l = tile j element (row = l>>2, col = l&3).
__device__ __forceinline__ void ldsm_x4(uint32_t& r0, uint32_t& r1,
                                        uint32_t& r2, uint32_t& r3,
                                        const uint32_t* p) {
    uint32_t addr = (uint32_t)__cvta_generic_to_shared(p);
    asm volatile(
        "ldmatrix.sync.aligned.m8n8.x4.shared.b16 {%0,%1,%2,%3}, [%4];"
        : "=r"(r0), "=r"(r1), "=r"(r2), "=r"(r3) : "r"(addr));
}

// ---------------------------------------------------------------------------
// TF32 GEMM 128x128 tile, Ktile=32, 8 warps (64x32 warp tile).
// Double-buffered smem, register prefetch, ldmatrix A-fragments.
// EPI: 1 = qkv scatter (A = x, Nn=2304), 0 = proj (A = g_attn, Nn=768).
// ---------------------------------------------------------------------------
#define AS_STR 36
#define BS_STR 136
#define AS_WORDS (128 * AS_STR)   // 4608
#define BS_WORDS (32 * BS_STR)    // 4352
#define GEMM_SMEM_WORDS (2 * (AS_WORDS + BS_WORDS))  // 17920 words = 71680 B

template <int EPI>
__global__ __launch_bounds__(256, 2) void gemm_tf32(
    const float* __restrict__ Ain, const float* __restrict__ Bm,
    const float* __restrict__ bias, float* __restrict__ out)
{
    const int K = ED;
    const int Nn = EPI ? 2304 : 768;
    // CRITICAL: reference g_attn from DEVICE code (host-passed __device__
    // symbol address is the host shadow — reads zeros via ATS).
    const float* A = EPI ? Ain : (const float*)g_attn;
    extern __shared__ uint32_t sm[];

    const int tid = threadIdx.x;
    const int lane = tid & 31, wid = tid >> 5;
    const int wm = wid >> 2, wn = wid & 3;
    const int q = lane >> 2, t = lane & 3;
    const int m0 = blockIdx.y * 128, n0 = blockIdx.x * 128;

    // ldmatrix per-lane offsets for A-fragments
    const int a_r = (lane & 7) + (((lane >> 3) & 1) << 3);  // 0..15
    const int a_c = (lane >> 4) << 2;                        // 0 or 4

    float acc[4][4][4];
#pragma unroll
    for (int i = 0; i < 4; i++)
#pragma unroll
        for (int j = 0; j < 4; j++)
#pragma unroll
            for (int r = 0; r < 4; r++) acc[i][j][r] = 0.0f;

    // loader coords
    const int ar = tid >> 3;            // +32*l -> row 0..127
    const int ac = (tid & 7) * 4;       // k-col 0..28
    const int bk = tid >> 5;            // +8*l -> k-row 0..31
    const int bc = (tid & 31) * 4;      // n-col 0..124

    float4 pa[4], pb[4];
#pragma unroll
    for (int l = 0; l < 4; l++) {
        pa[l] = *(const float4*)&A[(size_t)(m0 + ar + 32 * l) * K + ac];
        pb[l] = *(const float4*)&Bm[(size_t)(bk + 8 * l) * Nn + n0 + bc];
    }

    for (int it = 0; it < 24; it++) {
        uint32_t* As = sm + (it & 1) * (AS_WORDS + BS_WORDS);
        uint32_t* Bs = As + AS_WORDS;

        // ---- STS converted tile ----
#pragma unroll
        for (int l = 0; l < 4; l++) {
            int r = ar + 32 * l;
            uint4 w = make_uint4(f2tf(pa[l].x), f2tf(pa[l].y),
                                 f2tf(pa[l].z), f2tf(pa[l].w));
            *(uint4*)&As[r * AS_STR + ac] = w;
        }
#pragma unroll
        for (int l = 0; l < 4; l++) {
            int kr = bk + 8 * l;
            uint4 w = make_uint4(f2tf(pb[l].x), f2tf(pb[l].y),
                                 f2tf(pb[l].z), f2tf(pb[l].w));
            *(uint4*)&Bs[kr * BS_STR + bc] = w;
        }
        __syncthreads();

        // ---- prefetch next tile ----
        if (it < 23) {
            int k0 = (it + 1) * 32;
#pragma unroll
            for (int l = 0; l < 4; l++) {
                pa[l] = *(const float4*)&A[(size_t)(m0 + ar + 32 * l) * K + k0 + ac];
                pb[l] = *(const float4*)&Bm[(size_t)(k0 + bk + 8 * l) * Nn + n0 + bc];
            }
        }

        // ---- compute ----
#pragma unroll
        for (int ks = 0; ks < 4; ks++) {
            int kk = ks * 8;
            uint32_t b0[4], b1[4];
#pragma unroll
            for (int nt = 0; nt < 4; nt++) {
                int cb = wn * 32 + nt * 8 + q;
                b0[nt] = Bs[(kk + t) * BS_STR + cb];
                b1[nt] = Bs[(kk + 4 + t) * BS_STR + cb];
            }
#pragma unroll
            for (int mt = 0; mt < 4; mt++) {
                uint32_t x, y, z, v;
                ldsm_x4(x, y, z, v,
                        &As[(wm * 64 + mt * 16 + a_r) * AS_STR + kk + a_c]);
#pragma unroll
                for (int nt = 0; nt < 4; nt++)
                    mma_tf32(acc[mt][nt], x, y, z, v, b0[nt], b1[nt]);
            }
        }
        __syncthreads();
    }

    // ---- epilogue ----
#pragma unroll
    for (int mt = 0; mt < 4; mt++) {
#pragma unroll
        for (int half = 0; half < 2; half++) {
            int row = m0 + wm * 64 + mt * 16 + q + half * 8;
#pragma unroll
            for (int nt = 0; nt < 4; nt++) {
                int n = n0 + wn * 32 + nt * 8 + 2 * t;
                float c0 = acc[mt][nt][half * 2 + 0] + bias[n];
                float c1 = acc[mt][nt][half * 2 + 1] + bias[n + 1];
                if (EPI) {
                    int b = row >> 10, nn = row & 1023;
                    int which = n / ED;
                    int e = n - which * ED;
                    int h = e >> 6, d = e & 63;
                    float* dst = (which == 0) ? g_q
                               : ((which == 1) ? g_k : g_v);
                    *(float2*)&dst[((((size_t)b * NH + h) * SEQ + nn) << 6) + d] =
                        make_float2(c0, c1);
                } else {
                    *(float2*)&out[(size_t)row * Nn + n] = make_float2(c0, c1);
                }
            }
        }
    }
}

// ---------------------------------------------------------------------------
// Flash attention (round-2 layouts). Block = 128 Q rows x (b,h), 8 warps,
// warp w owns rows [16w,16w+16). KV tiles of 64. ldmatrix for Q/P/K frags.
// ---------------------------------------------------------------------------
#define QS_STR 68
#define KS_STR 68
#define VS_STR 72
#define PS_STR 68
#define SM_QS 0
#define SM_KS (128 * QS_STR)
#define SM_VS (SM_KS + 64 * KS_STR)
#define SM_PS (SM_VS + 64 * VS_STR)
#define ATTN_SMEM_WORDS (SM_PS + 128 * PS_STR)

__global__ __launch_bounds__(256, 2) void attn_kernel()
{
    extern __shared__ uint32_t sm[];
    uint32_t* Qs = sm + SM_QS;
    uint32_t* Ks = sm + SM_KS;
    uint32_t* Vs = sm + SM_VS;
    uint32_t* Ps = sm + SM_PS;

    const int tid = threadIdx.x;
    const int lane = tid & 31, w = tid >> 5;
    const int q = lane >> 2, t = lane & 3;
    const int n0 = blockIdx.x * 128;
    const int bh = blockIdx.z * NH + blockIdx.y;
    const int mb = w * 16;

    // ldmatrix per-lane offsets
    const int a_r = (lane & 7) + (((lane >> 3) & 1) << 3);   // a-frag row 0..15
    const int a_c = (lane >> 4) << 2;                        // a-frag col 0/4
    const int b_r = (lane & 7) + (((lane >> 4) & 1) << 3);   // b-frag row 0..15
    const int b_c = ((lane >> 3) & 1) << 2;                  // b-frag col 0/4

    const float* Q  = g_q + (size_t)bh * SEQ * HD;
    const float* Kg = g_k + (size_t)bh * SEQ * HD;
    const float* Vg = g_v + (size_t)bh * SEQ * HD;

    // Load Q tile (128x64), convert to tf32
#pragma unroll
    for (int l = 0; l < 8; l++) {
        int lin = tid + 256 * l;
        int r = lin >> 4, c = (lin & 15) * 4;
        float4 v = *(const float4*)&Q[(size_t)(n0 + r) * HD + c];
        Qs[r * QS_STR + c + 0] = f2tf(v.x);
        Qs[r * QS_STR + c + 1] = f2tf(v.y);
        Qs[r * QS_STR + c + 2] = f2tf(v.z);
        Qs[r * QS_STR + c + 3] = f2tf(v.w);
    }

    float oacc[8][4];
#pragma unroll
    for (int nt = 0; nt < 8; nt++)
#pragma unroll
        for (int r = 0; r < 4; r++) oacc[nt][r] = 0.0f;
    float m0_ = -1e30f, m1_ = -1e30f, l0_ = 0.0f, l1_ = 0.0f;

    const float sc = 0.125f * 1.4426950408889634f;  // scale * log2(e)

    for (int j0 = 0; j0 < SEQ; j0 += 64) {
        __syncthreads();   // protect Ks/Vs from previous iteration readers
#pragma unroll
        for (int l = 0; l < 4; l++) {
            int lin = tid + 256 * l;
            int r = lin >> 4, c = (lin & 15) * 4;
            float4 kv = *(const float4*)&Kg[(size_t)(j0 + r) * HD + c];
            Ks[r * KS_STR + c + 0] = f2tf(kv.x);
            Ks[r * KS_STR + c + 1] = f2tf(kv.y);
            Ks[r * KS_STR + c + 2] = f2tf(kv.z);
            Ks[r * KS_STR + c + 3] = f2tf(kv.w);
            float4 vv = *(const float4*)&Vg[(size_t)(j0 + r) * HD + c];
            Vs[r * VS_STR + c + 0] = f2tf(vv.x);
            Vs[r * VS_STR + c + 1] = f2tf(vv.y);
            Vs[r * VS_STR + c + 2] = f2tf(vv.z);
            Vs[r * VS_STR + c + 3] = f2tf(vv.w);
        }
        __syncthreads();

        // ---- S = Q K^T  (warp: 16 rows x 64 cols) ----
        float sacc[8][4];
#pragma unroll
        for (int nt = 0; nt < 8; nt++)
#pragma unroll
            for (int r = 0; r < 4; r++) sacc[nt][r] = 0.0f;

#pragma unroll
        for (int ks = 0; ks < 8; ks++) {
            int kk = ks * 8;
            uint32_t x, y, z, v;
            ldsm_x4(x, y, z, v, &Qs[(mb + a_r) * QS_STR + kk + a_c]);
#pragma unroll
            for (int ntp = 0; ntp < 4; ntp++) {
                uint32_t u0, u1, u2, u3;
                ldsm_x4(u0, u1, u2, u3,
                        &Ks[(ntp * 16 + b_r) * KS_STR + kk + b_c]);
                mma_tf32(sacc[2 * ntp + 0], x, y, z, v, u0, u1);
                mma_tf32(sacc[2 * ntp + 1], x, y, z, v, u2, u3);
            }
        }

#pragma unroll
        for (int nt = 0; nt < 8; nt++)
#pragma unroll
            for (int r = 0; r < 4; r++) sacc[nt][r] *= sc;

        // ---- online softmax ----
        float mx0 = -1e30f, mx1 = -1e30f;
#pragma unroll
        for (int nt = 0; nt < 8; nt++) {
            mx0 = fmaxf(mx0, fmaxf(sacc[nt][0], sacc[nt][1]));
            mx1 = fmaxf(mx1, fmaxf(sacc[nt][2], sacc[nt][3]));
        }
#pragma unroll
        for (int off = 1; off <= 2; off <<= 1) {
            mx0 = fmaxf(mx0, __shfl_xor_sync(0xffffffffu, mx0, off));
            mx1 = fmaxf(mx1, __shfl_xor_sync(0xffffffffu, mx1, off));
        }
        float mn0 = fmaxf(m0_, mx0), mn1 = fmaxf(m1_, mx1);
        float corr0 = exp2f(m0_ - mn0), corr1 = exp2f(m1_ - mn1);
        m0_ = mn0; m1_ = mn1;

        float rs0 = 0.0f, rs1 = 0.0f;
#pragma unroll
        for (int nt = 0; nt < 8; nt++) {
            float p0 = exp2f(sacc[nt][0] - mn0);
            float p1 = exp2f(sacc[nt][1] - mn0);
            float p2 = exp2f(sacc[nt][2] - mn1);
            float p3 = exp2f(sacc[nt][3] - mn1);
            rs0 += p0 + p1;
            rs1 += p2 + p3;
            *(uint2*)&Ps[(mb + q) * PS_STR + nt * 8 + 2 * t] =
                make_uint2(f2tf(p0), f2tf(p1));
            *(uint2*)&Ps[(mb + 8 + q) * PS_STR + nt * 8 + 2 * t] =
                make_uint2(f2tf(p2), f2tf(p3));
        }
#pragma unroll
        for (int off = 1; off <= 2; off <<= 1) {
            rs0 += __shfl_xor_sync(0xffffffffu, rs0, off);
            rs1 += __shfl_xor_sync(0xffffffffu, rs1, off);
        }
        l0_ = l0_ * corr0 + rs0;
        l1_ = l1_ * corr1 + rs1;
#pragma unroll
        for (int nt = 0; nt < 8; nt++) {
            oacc[nt][0] *= corr0;
            oacc[nt][1] *= corr0;
            oacc[nt][2] *= corr1;
            oacc[nt][3] *= corr1;
        }
        __syncwarp();

        // ---- O += P @ V ----
#pragma unroll
        for (int ks = 0; ks < 8; ks++) {
            int kk = ks * 8;
            uint32_t x, y, z, v;
            ldsm_x4(x, y, z, v, &Ps[(mb + a_r) * PS_STR + kk + a_c]);
#pragma unroll
            for (int nt = 0; nt < 8; nt++) {
                int nb = nt * 8 + q;
                uint32_t u0 = Vs[(kk + t) * VS_STR + nb];
                uint32_t u1 = Vs[(kk + 4 + t) * VS_STR + nb];
                mma_tf32(oacc[nt], x, y, z, v, u0, u1);
            }
        }
    }

    // ---- normalize + write to g_attn [B, N, H*D] ----
    float inv0 = 1.0f / l0_, inv1 = 1.0f / l1_;
    int row0 = n0 + mb + q, row1 = row0 + 8;
    size_t base0 = ((size_t)blockIdx.z * SEQ + row0) * ED + blockIdx.y * HD;
    size_t base1 = ((size_t)blockIdx.z * SEQ + row1) * ED + blockIdx.y * HD;
#pragma unroll
    for (int nt = 0; nt < 8; nt++) {
        int col = nt * 8 + 2 * t;
        *(float2*)&g_attn[base0 + col] =
            make_float2(oacc[nt][0] * inv0, oacc[nt][1] * inv0);
        *(float2*)&g_attn[base1 + col] =
            make_float2(oacc[nt][2] * inv1, oacc[nt][3] * inv1);
    }
}

// ---------------------------------------------------------------------------
extern "C" void kernel_launch(void* const* d_in, const int* in_sizes, int n_in,
                              void* d_out, int out_size)
{
    const float* x      = (const float*)d_in[0];
    const float* w_qkv  = (const float*)d_in[1];
    const float* b_qkv  = (const float*)d_in[2];
    const float* w_proj = (const float*)d_in[3];
    const float* b_proj = (const float*)d_in[4];
    float* out = (float*)d_out;

    size_t gsmem = (size_t)GEMM_SMEM_WORDS * 4;   // 71680 B
    cudaFuncSetAttribute(gemm_tf32<1>,
                         cudaFuncAttributeMaxDynamicSharedMemorySize, (int)gsmem);
    cudaFuncSetAttribute(gemm_tf32<0>,
                         cudaFuncAttributeMaxDynamicSharedMemorySize, (int)gsmem);

    dim3 g1((3 * ED) / 128, (NB * SEQ) / 128);   // (18, 128)
    gemm_tf32<1><<<g1, 256, gsmem>>>(x, w_qkv, b_qkv, nullptr);

    size_t asmem = (size_t)ATTN_SMEM_WORDS * 4;  // ~105 KB
    cudaFuncSetAttribute(attn_kernel,
                         cudaFuncAttributeMaxDynamicSharedMemorySize, (int)asmem);
    attn_kernel<<<dim3(SEQ / 128, NH, NB), 256, asmem>>>();

    dim3 g3(ED / 128, (NB * SEQ) / 128);         // (6, 128)
    gemm_tf32<0><<<g3, 256, gsmem>>>(nullptr, w_proj, b_proj, out);
}

// round 8
// speedup vs baseline: 4.5972x; 1.1301x over previous
#include <cuda_runtime.h>
#include <math.h>
#include <stdint.h>

#define NB  16
#define NH  12
#define SEQ 1024
#define HD  64
#define ED  768

// All scratch holds tf32-bit patterns (valid fp32), converted once at produce time.
__device__ float g_x[(size_t)NB * SEQ * ED];
__device__ float g_q[(size_t)NB * NH * SEQ * HD];
__device__ float g_k[(size_t)NB * NH * SEQ * HD];
__device__ float g_v[(size_t)NB * NH * SEQ * HD];
__device__ float g_attn[(size_t)NB * SEQ * ED];
__device__ float g_wqkv_t[(size_t)3 * ED * ED];   // [2304][768] tf32
__device__ float g_wproj_t[(size_t)ED * ED];      // [768][768] tf32

__device__ __forceinline__ uint32_t f2tf(float f) {
    uint32_t u;
    asm("cvt.rna.tf32.f32 %0, %1;" : "=r"(u) : "f"(f));
    return u;
}

__device__ __forceinline__ void mma_tf32(float* c, uint32_t a0, uint32_t a1,
                                         uint32_t a2, uint32_t a3,
                                         uint32_t b0, uint32_t b1) {
    asm volatile(
        "mma.sync.aligned.m16n8k8.row.col.f32.tf32.tf32.f32 "
        "{%0,%1,%2,%3}, {%4,%5,%6,%7}, {%8,%9}, {%0,%1,%2,%3};\n"
        : "+f"(c[0]), "+f"(c[1]), "+f"(c[2]), "+f"(c[3])
        : "r"(a0), "r"(a1), "r"(a2), "r"(a3), "r"(b0), "r"(b1));
}

__device__ __forceinline__ void ldsm_x4(uint32_t& r0, uint32_t& r1,
                                        uint32_t& r2, uint32_t& r3,
                                        const uint32_t* p) {
    uint32_t addr = (uint32_t)__cvta_generic_to_shared(p);
    asm volatile(
        "ldmatrix.sync.aligned.m8n8.x4.shared.b16 {%0,%1,%2,%3}, [%4];"
        : "=r"(r0), "=r"(r1), "=r"(r2), "=r"(r3) : "r"(addr));
}

#define CP_ASYNC16(dst, src) \
    asm volatile("cp.async.cg.shared.global [%0], [%1], 16;" \
                 :: "r"(dst), "l"(src) : "memory")
#define CP_COMMIT() asm volatile("cp.async.commit_group;" ::: "memory")
#define CP_WAIT0()  asm volatile("cp.async.wait_group 0;" ::: "memory")
#define CP_WAIT1()  asm volatile("cp.async.wait_group 1;" ::: "memory")

__device__ __forceinline__ uint32_t smem_addr(const void* p) {
    return (uint32_t)__cvta_generic_to_shared(p);
}

// ---------------------------------------------------------------------------
// Pre-pass kernels
// ---------------------------------------------------------------------------
__global__ void cvt_x_kernel(const float* __restrict__ x)
{
    size_t i = ((size_t)blockIdx.x * 256 + threadIdx.x) * 4;
    float4 v = *(const float4*)&x[i];
    *(uint4*)&g_x[i] = make_uint4(f2tf(v.x), f2tf(v.y), f2tf(v.z), f2tf(v.w));
}

template <int WHICH>  // 0: w_qkv (C=2304), 1: w_proj (C=768)
__global__ void transpose_cvt_kernel(const float* __restrict__ in)
{
    __shared__ float tile[32][33];
    const int R = ED;
    const int C = WHICH ? ED : 3 * ED;
    float* outp = WHICH ? g_wproj_t : g_wqkv_t;
    int bx = blockIdx.x * 32, by = blockIdx.y * 32;
    int x = bx + threadIdx.x;
#pragma unroll
    for (int j = 0; j < 32; j += 8) {
        int y = by + threadIdx.y + j;
        tile[threadIdx.y + j][threadIdx.x] = in[(size_t)y * C + x];
    }
    __syncthreads();
    int x2 = by + threadIdx.x;
#pragma unroll
    for (int j = 0; j < 32; j += 8) {
        int y2 = bx + threadIdx.y + j;
        outp[(size_t)y2 * R + x2] =
            __uint_as_float(f2tf(tile[threadIdx.x][threadIdx.y + j]));
    }
}

// ---------------------------------------------------------------------------
// TF32 GEMM 128x128 tile, Ktile=32, 8 warps (64x32 warp tile).
// cp.async double-buffered; A and B both [row][k] stride-36, frags via ldsm.
// EPI: 1 = qkv (A=g_x, B=g_wqkv_t, scatter tf32), 0 = proj (A=g_attn, out fp32).
// ---------------------------------------------------------------------------
#define TS_STR 36
#define TILE_WORDS (128 * TS_STR)                 // 4608
#define GBUF_WORDS (2 * TILE_WORDS)               // A + B per stage
#define GEMM_SMEM_WORDS (2 * GBUF_WORDS)          // 18432 words = 73728 B

template <int EPI>
__global__ __launch_bounds__(256, 2) void gemm_tc(
    const float* __restrict__ bias, float* __restrict__ out)
{
    const int K = ED;
    const float* A  = EPI ? (const float*)g_x : (const float*)g_attn;
    const float* Bt = EPI ? (const float*)g_wqkv_t : (const float*)g_wproj_t;
    extern __shared__ uint32_t sm[];

    const int tid = threadIdx.x;
    const int lane = tid & 31, wid = tid >> 5;
    const int wm = wid >> 2, wn = wid & 3;
    const int q = lane >> 2, t = lane & 3;
    const int m0 = blockIdx.y * 128, n0 = blockIdx.x * 128;

    const int a_r = (lane & 7) + (((lane >> 3) & 1) << 3);
    const int a_c = (lane >> 4) << 2;
    const int b_r = (lane & 7) + (((lane >> 4) & 1) << 3);
    const int b_c = ((lane >> 3) & 1) << 2;

    // loader coords: 1024 16B-chunks per 128x32 tile -> 4 per thread
    const int lrow = tid >> 3;          // +32*l -> rows 0..127
    const int lkc  = (tid & 7) * 4;

    float acc[4][4][4];
#pragma unroll
    for (int i = 0; i < 4; i++)
#pragma unroll
        for (int j = 0; j < 4; j++)
#pragma unroll
            for (int r = 0; r < 4; r++) acc[i][j][r] = 0.0f;

    const uint32_t sbase = smem_addr(sm);

    auto issue = [&](int it) {
        int k0 = it * 32;
        uint32_t abase = sbase + (uint32_t)(it & 1) * (GBUF_WORDS * 4);
        uint32_t bbase = abase + TILE_WORDS * 4;
#pragma unroll
        for (int l = 0; l < 4; l++) {
            int row = lrow + 32 * l;
            CP_ASYNC16(abase + (row * TS_STR + lkc) * 4,
                       &A[(size_t)(m0 + row) * K + k0 + lkc]);
            CP_ASYNC16(bbase + (row * TS_STR + lkc) * 4,
                       &Bt[(size_t)(n0 + row) * K + k0 + lkc]);
        }
        CP_COMMIT();
    };

    issue(0);

    for (int it = 0; it < 24; it++) {
        __syncthreads();                 // compute(it-1) done by all warps
        if (it + 1 < 24) { issue(it + 1); CP_WAIT1(); }
        else             { CP_WAIT0(); }
        __syncthreads();                 // tile `it` visible to all

        uint32_t* As = sm + (it & 1) * GBUF_WORDS;
        uint32_t* Bs = As + TILE_WORDS;

#pragma unroll
        for (int ks = 0; ks < 4; ks++) {
            int kk = ks * 8;
            uint32_t bb[4][2];
#pragma unroll
            for (int ntp = 0; ntp < 2; ntp++) {
                uint32_t u0, u1, u2, u3;
                ldsm_x4(u0, u1, u2, u3,
                        &Bs[(wn * 32 + ntp * 16 + b_r) * TS_STR + kk + b_c]);
                bb[2 * ntp + 0][0] = u0; bb[2 * ntp + 0][1] = u1;
                bb[2 * ntp + 1][0] = u2; bb[2 * ntp + 1][1] = u3;
            }
#pragma unroll
            for (int mt = 0; mt < 4; mt++) {
                uint32_t x, y, z, v;
                ldsm_x4(x, y, z, v,
                        &As[(wm * 64 + mt * 16 + a_r) * TS_STR + kk + a_c]);
#pragma unroll
                for (int nt = 0; nt < 4; nt++)
                    mma_tf32(acc[mt][nt], x, y, z, v, bb[nt][0], bb[nt][1]);
            }
        }
    }

    // ---- epilogue ----
#pragma unroll
    for (int mt = 0; mt < 4; mt++) {
#pragma unroll
        for (int half = 0; half < 2; half++) {
            int row = m0 + wm * 64 + mt * 16 + q + half * 8;
#pragma unroll
            for (int nt = 0; nt < 4; nt++) {
                int n = n0 + wn * 32 + nt * 8 + 2 * t;
                float c0 = acc[mt][nt][half * 2 + 0] + bias[n];
                float c1 = acc[mt][nt][half * 2 + 1] + bias[n + 1];
                if (EPI) {
                    int b = row >> 10, nn = row & 1023;
                    int which = n / ED;
                    int e = n - which * ED;
                    int h = e >> 6, d = e & 63;
                    float* dst = (which == 0) ? g_q
                               : ((which == 1) ? g_k : g_v);
                    // store tf32 bits — consumers use these only as mma operands
                    *(float2*)&dst[((((size_t)b * NH + h) * SEQ + nn) << 6) + d] =
                        make_float2(__uint_as_float(f2tf(c0)),
                                    __uint_as_float(f2tf(c1)));
                } else {
                    *(float2*)&out[(size_t)row * ED + n] = make_float2(c0, c1);
                }
            }
        }
    }
}

// ---------------------------------------------------------------------------
// Flash attention. Block = 128 Q rows x (b,h), 8 warps, warp w rows [16w,16w+16).
// Q fragments in registers; K/V cp.async double-buffered; KV tiles of 64.
// ---------------------------------------------------------------------------
#define KS_STR 68
#define VS_STR 72
#define PS_STR 68
#define KV_WORDS (64 * KS_STR + 64 * VS_STR)      // 8960 per stage
#define SM_P (2 * KV_WORDS)                       // 17920
#define ATTN_SMEM_WORDS (SM_P + 128 * PS_STR)     // 26624 words = 106496 B

__global__ __launch_bounds__(256, 2) void attn_kernel()
{
    extern __shared__ uint32_t sm[];
    uint32_t* Ps = sm + SM_P;

    const int tid = threadIdx.x;
    const int lane = tid & 31, w = tid >> 5;
    const int q = lane >> 2, t = lane & 3;
    const int n0 = blockIdx.x * 128;
    const int bh = blockIdx.z * NH + blockIdx.y;
    const int mb = w * 16;

    const int a_r = (lane & 7) + (((lane >> 3) & 1) << 3);
    const int a_c = (lane >> 4) << 2;
    const int b_r = (lane & 7) + (((lane >> 4) & 1) << 3);
    const int b_c = ((lane >> 3) & 1) << 2;

    const float* Q  = g_q + (size_t)bh * SEQ * HD;
    const float* Kg = g_k + (size_t)bh * SEQ * HD;
    const float* Vg = g_v + (size_t)bh * SEQ * HD;

    const uint32_t sbase = smem_addr(sm);

    // KV loader: 64 rows x 16 chunks = 1024 chunks per tile -> 4 per thread
    const int krow = tid >> 4;            // +16*l -> rows 0..63
    const int kkc  = (tid & 15) * 4;

    auto issueKV = [&](int j) {
        int j0 = j * 64;
        uint32_t kb = sbase + (uint32_t)(j & 1) * (KV_WORDS * 4);
        uint32_t vb = kb + 64 * KS_STR * 4;
#pragma unroll
        for (int l = 0; l < 4; l++) {
            int row = krow + 16 * l;      // FIXED: covers rows 0..63
            CP_ASYNC16(kb + (row * KS_STR + kkc) * 4,
                       &Kg[(size_t)(j0 + row) * HD + kkc]);
            CP_ASYNC16(vb + (row * VS_STR + kkc) * 4,
                       &Vg[(size_t)(j0 + row) * HD + kkc]);
        }
        CP_COMMIT();
    };

    // ---- stage Q through P buffer, hoist fragments to registers ----
    {
        uint32_t pb = sbase + SM_P * 4;
        // 128 rows x 16 chunks = 2048 chunks -> 8 per thread
#pragma unroll
        for (int l = 0; l < 8; l++) {
            int c = tid + 256 * l;
            int row = c >> 4, kc = (c & 15) * 4;
            CP_ASYNC16(pb + (row * PS_STR + kc) * 4,
                       &Q[(size_t)(n0 + row) * HD + kc]);
        }
        CP_COMMIT();
        issueKV(0);           // groups pending: {Q, KV0}
        CP_WAIT1();           // Q complete
        __syncthreads();
    }

    uint32_t qf[8][4];
#pragma unroll
    for (int ks = 0; ks < 8; ks++)
        ldsm_x4(qf[ks][0], qf[ks][1], qf[ks][2], qf[ks][3],
                &Ps[(mb + a_r) * PS_STR + ks * 8 + a_c]);

    float oacc[8][4];
#pragma unroll
    for (int nt = 0; nt < 8; nt++)
#pragma unroll
        for (int r = 0; r < 4; r++) oacc[nt][r] = 0.0f;
    float m0_ = -1e30f, m1_ = -1e30f, l0_ = 0.0f, l1_ = 0.0f;

    const float sc = 0.125f * 1.4426950408889634f;

    for (int j = 0; j < SEQ / 64; j++) {
        __syncthreads();                       // compute(j-1) done (also Q extract)
        if (j + 1 < SEQ / 64) { issueKV(j + 1); CP_WAIT1(); }
        else                  { CP_WAIT0(); }
        __syncthreads();                       // KV(j) visible

        uint32_t* Ks = sm + (j & 1) * KV_WORDS;
        uint32_t* Vs = Ks + 64 * KS_STR;

        // ---- S = Q K^T ----
        float sacc[8][4];
#pragma unroll
        for (int nt = 0; nt < 8; nt++)
#pragma unroll
            for (int r = 0; r < 4; r++) sacc[nt][r] = 0.0f;

#pragma unroll
        for (int ks = 0; ks < 8; ks++) {
            int kk = ks * 8;
#pragma unroll
            for (int ntp = 0; ntp < 4; ntp++) {
                uint32_t u0, u1, u2, u3;
                ldsm_x4(u0, u1, u2, u3,
                        &Ks[(ntp * 16 + b_r) * KS_STR + kk + b_c]);
                mma_tf32(sacc[2 * ntp + 0], qf[ks][0], qf[ks][1], qf[ks][2],
                         qf[ks][3], u0, u1);
                mma_tf32(sacc[2 * ntp + 1], qf[ks][0], qf[ks][1], qf[ks][2],
                         qf[ks][3], u2, u3);
            }
        }

#pragma unroll
        for (int nt = 0; nt < 8; nt++)
#pragma unroll
            for (int r = 0; r < 4; r++) sacc[nt][r] *= sc;

        // ---- online softmax ----
        float mx0 = -1e30f, mx1 = -1e30f;
#pragma unroll
        for (int nt = 0; nt < 8; nt++) {
            mx0 = fmaxf(mx0, fmaxf(sacc[nt][0], sacc[nt][1]));
            mx1 = fmaxf(mx1, fmaxf(sacc[nt][2], sacc[nt][3]));
        }
#pragma unroll
        for (int off = 1; off <= 2; off <<= 1) {
            mx0 = fmaxf(mx0, __shfl_xor_sync(0xffffffffu, mx0, off));
            mx1 = fmaxf(mx1, __shfl_xor_sync(0xffffffffu, mx1, off));
        }
        float mn0 = fmaxf(m0_, mx0), mn1 = fmaxf(m1_, mx1);
        float corr0 = exp2f(m0_ - mn0), corr1 = exp2f(m1_ - mn1);
        m0_ = mn0; m1_ = mn1;

        float rs0 = 0.0f, rs1 = 0.0f;
#pragma unroll
        for (int nt = 0; nt < 8; nt++) {
            float p0 = exp2f(sacc[nt][0] - mn0);
            float p1 = exp2f(sacc[nt][1] - mn0);
            float p2 = exp2f(sacc[nt][2] - mn1);
            float p3 = exp2f(sacc[nt][3] - mn1);
            rs0 += p0 + p1;
            rs1 += p2 + p3;
            *(uint2*)&Ps[(mb + q) * PS_STR + nt * 8 + 2 * t] =
                make_uint2(f2tf(p0), f2tf(p1));
            *(uint2*)&Ps[(mb + 8 + q) * PS_STR + nt * 8 + 2 * t] =
                make_uint2(f2tf(p2), f2tf(p3));
        }
#pragma unroll
        for (int off = 1; off <= 2; off <<= 1) {
            rs0 += __shfl_xor_sync(0xffffffffu, rs0, off);
            rs1 += __shfl_xor_sync(0xffffffffu, rs1, off);
        }
        l0_ = l0_ * corr0 + rs0;
        l1_ = l1_ * corr1 + rs1;
#pragma unroll
        for (int nt = 0; nt < 8; nt++) {
            oacc[nt][0] *= corr0;
            oacc[nt][1] *= corr0;
            oacc[nt][2] *= corr1;
            oacc[nt][3] *= corr1;
        }
        __syncwarp();

        // ---- O += P @ V ----
#pragma unroll
        for (int ks = 0; ks < 8; ks++) {
            int kk = ks * 8;
            uint32_t x, y, z, v;
            ldsm_x4(x, y, z, v, &Ps[(mb + a_r) * PS_STR + kk + a_c]);
#pragma unroll
            for (int nt = 0; nt < 8; nt++) {
                int nb = nt * 8 + q;
                uint32_t u0 = Vs[(kk + t) * VS_STR + nb];
                uint32_t u1 = Vs[(kk + 4 + t) * VS_STR + nb];
                mma_tf32(oacc[nt], x, y, z, v, u0, u1);
            }
        }
    }

    // ---- normalize + write tf32 bits to g_attn ----
    float inv0 = 1.0f / l0_, inv1 = 1.0f / l1_;
    int row0 = n0 + mb + q, row1 = row0 + 8;
    size_t base0 = ((size_t)blockIdx.z * SEQ + row0) * ED + blockIdx.y * HD;
    size_t base1 = ((size_t)blockIdx.z * SEQ + row1) * ED + blockIdx.y * HD;
#pragma unroll
    for (int nt = 0; nt < 8; nt++) {
        int col = nt * 8 + 2 * t;
        *(uint2*)&g_attn[base0 + col] =
            make_uint2(f2tf(oacc[nt][0] * inv0), f2tf(oacc[nt][1] * inv0));
        *(uint2*)&g_attn[base1 + col] =
            make_uint2(f2tf(oacc[nt][2] * inv1), f2tf(oacc[nt][3] * inv1));
    }
}

// ---------------------------------------------------------------------------
extern "C" void kernel_launch(void* const* d_in, const int* in_sizes, int n_in,
                              void* d_out, int out_size)
{
    const float* x      = (const float*)d_in[0];
    const float* w_qkv  = (const float*)d_in[1];
    const float* b_qkv  = (const float*)d_in[2];
    const float* w_proj = (const float*)d_in[3];
    const float* b_proj = (const float*)d_in[4];
    float* out = (float*)d_out;

    // 0) convert/transpose inputs to tf32-at-rest
    cvt_x_kernel<<<(NB * SEQ * ED) / 1024, 256>>>(x);
    transpose_cvt_kernel<0><<<dim3((3 * ED) / 32, ED / 32), dim3(32, 8)>>>(w_qkv);
    transpose_cvt_kernel<1><<<dim3(ED / 32, ED / 32), dim3(32, 8)>>>(w_proj);

    size_t gsmem = (size_t)GEMM_SMEM_WORDS * 4;   // 73728 B
    cudaFuncSetAttribute(gemm_tc<1>,
                         cudaFuncAttributeMaxDynamicSharedMemorySize, (int)gsmem);
    cudaFuncSetAttribute(gemm_tc<0>,
                         cudaFuncAttributeMaxDynamicSharedMemorySize, (int)gsmem);

    // 1) QKV GEMM + bias + scatter (tf32 bits)
    dim3 g1((3 * ED) / 128, (NB * SEQ) / 128);
    gemm_tc<1><<<g1, 256, gsmem>>>(b_qkv, nullptr);

    // 2) Attention
    size_t asmem = (size_t)ATTN_SMEM_WORDS * 4;   // 106496 B
    cudaFuncSetAttribute(attn_kernel,
                         cudaFuncAttributeMaxDynamicSharedMemorySize, (int)asmem);
    attn_kernel<<<dim3(SEQ / 128, NH, NB), 256, asmem>>>();

    // 3) Projection
    dim3 g3(ED / 128, (NB * SEQ) / 128);
    gemm_tc<0><<<g3, 256, gsmem>>>(b_proj, out);
}

// round 9
// speedup vs baseline: 8.4744x; 1.8434x over previous
#include <cuda_runtime.h>
#include <cuda_fp16.h>
#include <math.h>
#include <stdint.h>

#define NB  16
#define NH  12
#define SEQ 1024
#define HD  64
#define ED  768

// All scratch at rest is fp16 (same 10-bit mantissa as tf32; fp32 accum).
__device__ __half g_x[(size_t)NB * SEQ * ED];
__device__ __half g_q[(size_t)NB * NH * SEQ * HD];
__device__ __half g_k[(size_t)NB * NH * SEQ * HD];
__device__ __half g_v[(size_t)NB * NH * SEQ * HD];
__device__ __half g_attn[(size_t)NB * SEQ * ED];
__device__ __half g_wqkv_t[(size_t)3 * ED * ED];   // [2304][768]
__device__ __half g_wproj_t[(size_t)ED * ED];      // [768][768]

__device__ __forceinline__ void mma_f16(float* c, uint32_t a0, uint32_t a1,
                                        uint32_t a2, uint32_t a3,
                                        uint32_t b0, uint32_t b1) {
    asm volatile(
        "mma.sync.aligned.m16n8k16.row.col.f32.f16.f16.f32 "
        "{%0,%1,%2,%3}, {%4,%5,%6,%7}, {%8,%9}, {%0,%1,%2,%3};\n"
        : "+f"(c[0]), "+f"(c[1]), "+f"(c[2]), "+f"(c[3])
        : "r"(a0), "r"(a1), "r"(a2), "r"(a3), "r"(b0), "r"(b1));
}

__device__ __forceinline__ void ldsm_x4(uint32_t& r0, uint32_t& r1,
                                        uint32_t& r2, uint32_t& r3,
                                        const __half* p) {
    uint32_t addr = (uint32_t)__cvta_generic_to_shared(p);
    asm volatile(
        "ldmatrix.sync.aligned.m8n8.x4.shared.b16 {%0,%1,%2,%3}, [%4];"
        : "=r"(r0), "=r"(r1), "=r"(r2), "=r"(r3) : "r"(addr));
}

__device__ __forceinline__ void ldsm_x4t(uint32_t& r0, uint32_t& r1,
                                         uint32_t& r2, uint32_t& r3,
                                         const __half* p) {
    uint32_t addr = (uint32_t)__cvta_generic_to_shared(p);
    asm volatile(
        "ldmatrix.sync.aligned.m8n8.x4.trans.shared.b16 {%0,%1,%2,%3}, [%4];"
        : "=r"(r0), "=r"(r1), "=r"(r2), "=r"(r3) : "r"(addr));
}

__device__ __forceinline__ uint32_t pack_h2(float a, float b) {
    __half2 h = __floats2half2_rn(a, b);
    return *(uint32_t*)&h;
}

#define CP_ASYNC16(dst, src) \
    asm volatile("cp.async.cg.shared.global [%0], [%1], 16;" \
                 :: "r"(dst), "l"(src) : "memory")
#define CP_COMMIT() asm volatile("cp.async.commit_group;" ::: "memory")
#define CP_WAIT0()  asm volatile("cp.async.wait_group 0;" ::: "memory")
#define CP_WAIT1()  asm volatile("cp.async.wait_group 1;" ::: "memory")

__device__ __forceinline__ uint32_t smem_addr(const void* p) {
    return (uint32_t)__cvta_generic_to_shared(p);
}

// ---------------------------------------------------------------------------
// Pre-pass kernels: fp32 -> fp16 at rest
// ---------------------------------------------------------------------------
__global__ void cvt_x_kernel(const float* __restrict__ x)
{
    size_t i = ((size_t)blockIdx.x * 256 + threadIdx.x) * 4;
    float4 v = *(const float4*)&x[i];
    uint2 o;
    o.x = pack_h2(v.x, v.y);
    o.y = pack_h2(v.z, v.w);
    *(uint2*)&g_x[i] = o;
}

template <int WHICH>  // 0: w_qkv (C=2304), 1: w_proj (C=768)
__global__ void transpose_cvt_kernel(const float* __restrict__ in)
{
    __shared__ float tile[32][33];
    const int R = ED;
    const int C = WHICH ? ED : 3 * ED;
    __half* outp = WHICH ? g_wproj_t : g_wqkv_t;
    int bx = blockIdx.x * 32, by = blockIdx.y * 32;
    int x = bx + threadIdx.x;
#pragma unroll
    for (int j = 0; j < 32; j += 8) {
        int y = by + threadIdx.y + j;
        tile[threadIdx.y + j][threadIdx.x] = in[(size_t)y * C + x];
    }
    __syncthreads();
    int x2 = by + threadIdx.x;
#pragma unroll
    for (int j = 0; j < 32; j += 8) {
        int y2 = bx + threadIdx.y + j;
        outp[(size_t)y2 * R + x2] = __float2half_rn(tile[threadIdx.x][threadIdx.y + j]);
    }
}

// ---------------------------------------------------------------------------
// fp16 GEMM 128x128 tile, Ktile=64, 8 warps (64x32 warp tile), m16n8k16.
// cp.async double-buffered; A [m][k], B [n][k] both fp16 stride-72 halves.
// EPI: 1 = qkv (A=g_x, B=g_wqkv_t, scatter fp16), 0 = proj (A=g_attn, out fp32).
// ---------------------------------------------------------------------------
#define TSH 72
#define TILE_HALVES (128 * TSH)                   // 9216 halves = 18432 B
#define GBUF_BYTES (2 * TILE_HALVES * 2)          // A+B per stage = 36864 B
#define GEMM_SMEM_BYTES (2 * GBUF_BYTES)          // 73728 B

template <int EPI>
__global__ __launch_bounds__(256, 2) void gemm_f16(
    const float* __restrict__ bias, float* __restrict__ out)
{
    const int K = ED;
    const __half* A  = EPI ? (const __half*)g_x : (const __half*)g_attn;
    const __half* Bt = EPI ? (const __half*)g_wqkv_t : (const __half*)g_wproj_t;
    extern __shared__ __half smh[];

    const int tid = threadIdx.x;
    const int lane = tid & 31, wid = tid >> 5;
    const int wm = wid >> 2, wn = wid & 3;
    const int q = lane >> 2, t = lane & 3;
    const int m0 = blockIdx.y * 128, n0 = blockIdx.x * 128;

    // ldmatrix per-lane offsets (in halves)
    const int a_r = lane & 15;                     // A rows 0..15
    const int a_c = ((lane >> 4) & 1) << 3;        // A k-col 0/8
    const int b_r = (lane & 7) + (((lane >> 4) & 1) << 3);  // B n-row
    const int b_c = (((lane >> 3) & 1)) << 3;      // B k-col 0/8

    // loader: 128 rows x 8 chunks(16B=8h) = 1024 chunks -> 4/thread
    float acc[4][4][4];
#pragma unroll
    for (int i = 0; i < 4; i++)
#pragma unroll
        for (int j = 0; j < 4; j++)
#pragma unroll
            for (int r = 0; r < 4; r++) acc[i][j][r] = 0.0f;

    const uint32_t sbase = smem_addr(smh);

    auto issue = [&](int it) {
        int k0 = it * 64;
        uint32_t abase = sbase + (uint32_t)(it & 1) * GBUF_BYTES;
        uint32_t bbase = abase + TILE_HALVES * 2;
#pragma unroll
        for (int l = 0; l < 4; l++) {
            int c = tid + 256 * l;
            int row = c >> 3, kc = (c & 7) * 8;
            CP_ASYNC16(abase + (row * TSH + kc) * 2,
                       &A[(size_t)(m0 + row) * K + k0 + kc]);
            CP_ASYNC16(bbase + (row * TSH + kc) * 2,
                       &Bt[(size_t)(n0 + row) * K + k0 + kc]);
        }
        CP_COMMIT();
    };

    issue(0);

    for (int it = 0; it < 12; it++) {
        __syncthreads();
        if (it + 1 < 12) { issue(it + 1); CP_WAIT1(); }
        else             { CP_WAIT0(); }
        __syncthreads();

        __half* As = smh + (size_t)(it & 1) * (GBUF_BYTES / 2);
        __half* Bs = As + TILE_HALVES;

#pragma unroll
        for (int kc = 0; kc < 4; kc++) {          // 4 k16 chunks
            int kk = kc * 16;
            uint32_t bb[4][2];
#pragma unroll
            for (int ntp = 0; ntp < 2; ntp++) {
                uint32_t u0, u1, u2, u3;
                ldsm_x4(u0, u1, u2, u3,
                        &Bs[(wn * 32 + ntp * 16 + b_r) * TSH + kk + b_c]);
                bb[2 * ntp + 0][0] = u0; bb[2 * ntp + 0][1] = u1;
                bb[2 * ntp + 1][0] = u2; bb[2 * ntp + 1][1] = u3;
            }
#pragma unroll
            for (int mt = 0; mt < 4; mt++) {
                uint32_t x, y, z, v;
                ldsm_x4(x, y, z, v,
                        &As[(wm * 64 + mt * 16 + a_r) * TSH + kk + a_c]);
#pragma unroll
                for (int nt = 0; nt < 4; nt++)
                    mma_f16(acc[mt][nt], x, y, z, v, bb[nt][0], bb[nt][1]);
            }
        }
    }

    // ---- epilogue (acc layout: c0,c1 row q cols 2t,2t+1; c2,c3 row q+8) ----
#pragma unroll
    for (int mt = 0; mt < 4; mt++) {
#pragma unroll
        for (int half_ = 0; half_ < 2; half_++) {
            int row = m0 + wm * 64 + mt * 16 + q + half_ * 8;
#pragma unroll
            for (int nt = 0; nt < 4; nt++) {
                int n = n0 + wn * 32 + nt * 8 + 2 * t;
                float c0 = acc[mt][nt][half_ * 2 + 0] + bias[n];
                float c1 = acc[mt][nt][half_ * 2 + 1] + bias[n + 1];
                if (EPI) {
                    int b = row >> 10, nn = row & 1023;
                    int which = n / ED;
                    int e = n - which * ED;
                    int h = e >> 6, d = e & 63;
                    __half* dst = (which == 0) ? g_q
                                : ((which == 1) ? g_k : g_v);
                    __half2 hv = __floats2half2_rn(c0, c1);
                    *(__half2*)&dst[((((size_t)b * NH + h) * SEQ + nn) << 6) + d] = hv;
                } else {
                    *(float2*)&out[(size_t)row * ED + n] = make_float2(c0, c1);
                }
            }
        }
    }
}

// ---------------------------------------------------------------------------
// Flash attention fp16. Block = 128 Q rows x (b,h), 8 warps (16 rows each).
// Q frags in regs; K/V cp.async double-buffered; P->A operand in registers
// (FA2 layout trick), V B-frags via ldmatrix.x4.trans. No P smem.
// ---------------------------------------------------------------------------
#define KSH 72
#define KV_STAGE_HALVES (2 * 64 * KSH)            // K + V = 9216 halves
#define SM_Q_HALVES (2 * KV_STAGE_HALVES)         // 18432
#define ATTN_SMEM_BYTES ((SM_Q_HALVES + 128 * KSH) * 2)  // 55296 B

__global__ __launch_bounds__(256, 2) void attn_kernel()
{
    extern __shared__ __half smh[];
    __half* Qs = smh + SM_Q_HALVES;

    const int tid = threadIdx.x;
    const int lane = tid & 31, w = tid >> 5;
    const int q = lane >> 2, t = lane & 3;
    const int n0 = blockIdx.x * 128;
    const int bh = blockIdx.z * NH + blockIdx.y;
    const int mb = w * 16;

    const int a_r = lane & 15;
    const int a_c = ((lane >> 4) & 1) << 3;
    const int b_r = (lane & 7) + (((lane >> 4) & 1) << 3);
    const int b_c = (((lane >> 3) & 1)) << 3;
    // V trans-frag offsets: row k, col n
    const int v_r = (lane & 7) + (((lane >> 3) & 1) << 3);
    const int v_c = ((lane >> 4) & 1) << 3;

    const __half* Q  = g_q + (size_t)bh * SEQ * HD;
    const __half* Kg = g_k + (size_t)bh * SEQ * HD;
    const __half* Vg = g_v + (size_t)bh * SEQ * HD;

    const uint32_t sbase = smem_addr(smh);

    // KV loader: K/V each 64 rows x 8 chunks = 512 chunks -> 2/thread each
    auto issueKV = [&](int j) {
        int j0 = j * 64;
        uint32_t kb = sbase + (uint32_t)(j & 1) * (KV_STAGE_HALVES * 2);
        uint32_t vb = kb + 64 * KSH * 2;
#pragma unroll
        for (int l = 0; l < 2; l++) {
            int c = tid + 256 * l;
            int row = c >> 3, kc = (c & 7) * 8;
            CP_ASYNC16(kb + (row * KSH + kc) * 2,
                       &Kg[(size_t)(j0 + row) * HD + kc]);
            CP_ASYNC16(vb + (row * KSH + kc) * 2,
                       &Vg[(size_t)(j0 + row) * HD + kc]);
        }
        CP_COMMIT();
    };

    // ---- stage Q (128x64 fp16), hoist fragments ----
    {
        uint32_t qb = sbase + SM_Q_HALVES * 2;
#pragma unroll
        for (int l = 0; l < 4; l++) {
            int c = tid + 256 * l;
            int row = c >> 3, kc = (c & 7) * 8;
            CP_ASYNC16(qb + (row * KSH + kc) * 2,
                       &Q[(size_t)(n0 + row) * HD + kc]);
        }
        CP_COMMIT();
        issueKV(0);
        CP_WAIT1();
        __syncthreads();
    }

    uint32_t qf[4][4];
#pragma unroll
    for (int kc = 0; kc < 4; kc++)
        ldsm_x4(qf[kc][0], qf[kc][1], qf[kc][2], qf[kc][3],
                &Qs[(mb + a_r) * KSH + kc * 16 + a_c]);

    float oacc[8][4];
#pragma unroll
    for (int nt = 0; nt < 8; nt++)
#pragma unroll
        for (int r = 0; r < 4; r++) oacc[nt][r] = 0.0f;
    float m0_ = -1e30f, m1_ = -1e30f, l0_ = 0.0f, l1_ = 0.0f;

    const float sc = 0.125f * 1.4426950408889634f;

    for (int j = 0; j < SEQ / 64; j++) {
        __syncthreads();
        if (j + 1 < SEQ / 64) { issueKV(j + 1); CP_WAIT1(); }
        else                  { CP_WAIT0(); }
        __syncthreads();

        __half* Ks = smh + (size_t)(j & 1) * KV_STAGE_HALVES;
        __half* Vs = Ks + 64 * KSH;

        // ---- S = Q K^T ----
        float sacc[8][4];
#pragma unroll
        for (int nt = 0; nt < 8; nt++)
#pragma unroll
            for (int r = 0; r < 4; r++) sacc[nt][r] = 0.0f;

#pragma unroll
        for (int kc = 0; kc < 4; kc++) {
            int kk = kc * 16;
#pragma unroll
            for (int ntp = 0; ntp < 4; ntp++) {
                uint32_t u0, u1, u2, u3;
                ldsm_x4(u0, u1, u2, u3,
                        &Ks[(ntp * 16 + b_r) * KSH + kk + b_c]);
                mma_f16(sacc[2 * ntp + 0], qf[kc][0], qf[kc][1], qf[kc][2],
                        qf[kc][3], u0, u1);
                mma_f16(sacc[2 * ntp + 1], qf[kc][0], qf[kc][1], qf[kc][2],
                        qf[kc][3], u2, u3);
            }
        }

#pragma unroll
        for (int nt = 0; nt < 8; nt++)
#pragma unroll
            for (int r = 0; r < 4; r++) sacc[nt][r] *= sc;

        // ---- online softmax ----
        float mx0 = -1e30f, mx1 = -1e30f;
#pragma unroll
        for (int nt = 0; nt < 8; nt++) {
            mx0 = fmaxf(mx0, fmaxf(sacc[nt][0], sacc[nt][1]));
            mx1 = fmaxf(mx1, fmaxf(sacc[nt][2], sacc[nt][3]));
        }
#pragma unroll
        for (int off = 1; off <= 2; off <<= 1) {
            mx0 = fmaxf(mx0, __shfl_xor_sync(0xffffffffu, mx0, off));
            mx1 = fmaxf(mx1, __shfl_xor_sync(0xffffffffu, mx1, off));
        }
        float mn0 = fmaxf(m0_, mx0), mn1 = fmaxf(m1_, mx1);
        float corr0 = exp2f(m0_ - mn0), corr1 = exp2f(m1_ - mn1);
        m0_ = mn0; m1_ = mn1;

        float rs0 = 0.0f, rs1 = 0.0f;
        uint32_t plo[8], phi[8];   // half2 P: row q / row q+8
#pragma unroll
        for (int nt = 0; nt < 8; nt++) {
            float p0 = exp2f(sacc[nt][0] - mn0);
            float p1 = exp2f(sacc[nt][1] - mn0);
            float p2 = exp2f(sacc[nt][2] - mn1);
            float p3 = exp2f(sacc[nt][3] - mn1);
            rs0 += p0 + p1;
            rs1 += p2 + p3;
            plo[nt] = pack_h2(p0, p1);
            phi[nt] = pack_h2(p2, p3);
        }
#pragma unroll
        for (int off = 1; off <= 2; off <<= 1) {
            rs0 += __shfl_xor_sync(0xffffffffu, rs0, off);
            rs1 += __shfl_xor_sync(0xffffffffu, rs1, off);
        }
        l0_ = l0_ * corr0 + rs0;
        l1_ = l1_ * corr1 + rs1;
#pragma unroll
        for (int nt = 0; nt < 8; nt++) {
            oacc[nt][0] *= corr0;
            oacc[nt][1] *= corr0;
            oacc[nt][2] *= corr1;
            oacc[nt][3] *= corr1;
        }

        // ---- O += P @ V (A from registers, B via ldmatrix.trans) ----
#pragma unroll
        for (int ks = 0; ks < 4; ks++) {          // k16 chunks of seqpos
            uint32_t pa0 = plo[2 * ks + 0], pa1 = phi[2 * ks + 0];
            uint32_t pa2 = plo[2 * ks + 1], pa3 = phi[2 * ks + 1];
#pragma unroll
            for (int ntp = 0; ntp < 4; ntp++) {
                uint32_t r0, r1, r2, r3;
                ldsm_x4t(r0, r1, r2, r3,
                         &Vs[(ks * 16 + v_r) * KSH + ntp * 16 + v_c]);
                mma_f16(oacc[2 * ntp + 0], pa0, pa1, pa2, pa3, r0, r1);
                mma_f16(oacc[2 * ntp + 1], pa0, pa1, pa2, pa3, r2, r3);
            }
        }
    }

    // ---- normalize + write fp16 to g_attn ----
    float inv0 = 1.0f / l0_, inv1 = 1.0f / l1_;
    int row0 = n0 + mb + q, row1 = row0 + 8;
    size_t base0 = ((size_t)blockIdx.z * SEQ + row0) * ED + blockIdx.y * HD;
    size_t base1 = ((size_t)blockIdx.z * SEQ + row1) * ED + blockIdx.y * HD;
#pragma unroll
    for (int nt = 0; nt < 8; nt++) {
        int col = nt * 8 + 2 * t;
        *(__half2*)&g_attn[base0 + col] =
            __floats2half2_rn(oacc[nt][0] * inv0, oacc[nt][1] * inv0);
        *(__half2*)&g_attn[base1 + col] =
            __floats2half2_rn(oacc[nt][2] * inv1, oacc[nt][3] * inv1);
    }
}

// ---------------------------------------------------------------------------
extern "C" void kernel_launch(void* const* d_in, const int* in_sizes, int n_in,
                              void* d_out, int out_size)
{
    const float* x      = (const float*)d_in[0];
    const float* w_qkv  = (const float*)d_in[1];
    const float* b_qkv  = (const float*)d_in[2];
    const float* w_proj = (const float*)d_in[3];
    const float* b_proj = (const float*)d_in[4];
    float* out = (float*)d_out;

    // 0) convert/transpose inputs to fp16-at-rest
    cvt_x_kernel<<<(NB * SEQ * ED) / 1024, 256>>>(x);
    transpose_cvt_kernel<0><<<dim3((3 * ED) / 32, ED / 32), dim3(32, 8)>>>(w_qkv);
    transpose_cvt_kernel<1><<<dim3(ED / 32, ED / 32), dim3(32, 8)>>>(w_proj);

    cudaFuncSetAttribute(gemm_f16<1>,
                         cudaFuncAttributeMaxDynamicSharedMemorySize, GEMM_SMEM_BYTES);
    cudaFuncSetAttribute(gemm_f16<0>,
                         cudaFuncAttributeMaxDynamicSharedMemorySize, GEMM_SMEM_BYTES);

    // 1) QKV GEMM + bias + scatter (fp16)
    dim3 g1((3 * ED) / 128, (NB * SEQ) / 128);
    gemm_f16<1><<<g1, 256, GEMM_SMEM_BYTES>>>(b_qkv, nullptr);

    // 2) Attention
    cudaFuncSetAttribute(attn_kernel,
                         cudaFuncAttributeMaxDynamicSharedMemorySize, ATTN_SMEM_BYTES);
    attn_kernel<<<dim3(SEQ / 128, NH, NB), 256, ATTN_SMEM_BYTES>>>();

    // 3) Projection (out fp32)
    dim3 g3(ED / 128, (NB * SEQ) / 128);
    gemm_f16<0><<<g3, 256, GEMM_SMEM_BYTES>>>(b_proj, out);
}